// round 15
// baseline (speedup 1.0000x reference)
#include <cuda_runtime.h>

// B=16, C=4, H=1024, W=1024
// x: [B, C, H, W] fp32 ; out: [B, H, C, W] fp32
//
// Two-row CTA variant for DRAM granularity: one CTA per (b, h/2) handles rows
// h=2*h2 and h=2*h2+1. Per channel the CTA reads 8KB CONTIGUOUS (adjacent h
// rows) and writes 32KB contiguous. 512 threads: row = tid>>8, 256 thr/row x
// 4 w. Two independent reductions share ONE barrier pair (amortized).
// Register-lean via smem staging (R13 trick): regs ~40 -> 3 CTAs/SM (75% occ).

#define H_DIM 1024
#define W_DIM 1024
#define THREADS 512

__global__ __launch_bounds__(THREADS, 3)
void fused_attn_kernel(const float* __restrict__ x,
                       const float* __restrict__ wq, const float* __restrict__ bq,
                       const float* __restrict__ wk, const float* __restrict__ bk,
                       const float* __restrict__ wv, const float* __restrict__ bv,
                       float* __restrict__ out)
{
    const int tid  = threadIdx.x;
    const int lane = tid & 31;
    const int warp = tid >> 5;            // 0..15
    const int row  = tid >> 8;            // 0 or 1
    const int wrow = warp & 7;            // warp index within row group
    const int w0   = (tid & 255) << 2;    // 4 w per thread

    __shared__ float xt[2][4][W_DIM];     // 32KB staged x (2 rows x 4 ch)
    __shared__ float s_red[2][8][16];     // per-row, per-warp partials
    __shared__ float s_gm[2][16];
    __shared__ float s_sc[2][16];
    __shared__ float s_attn[2][16];
    __shared__ float s_fin[2][20];        // per-row A_eff[16] | b_eff[4]

    const int bh2 = blockIdx.x;           // b*512 + h2
    const int b   = bh2 >> 9;
    const int h   = ((bh2 & 511) << 1) | row;
    const int base = ((b << 2) * H_DIM + h) * W_DIM + w0;

    // ---- Load (streaming LDG.128), accumulate moments, stash to smem
    float r[16];
    #pragma unroll
    for (int i = 0; i < 16; i++) r[i] = 0.f;

    {
        float4 t[4];
        #pragma unroll
        for (int c = 0; c < 4; c++)
            t[c] = __ldcs(reinterpret_cast<const float4*>(
                       x + base + c * (H_DIM * W_DIM)));

        #pragma unroll
        for (int p = 0; p < 4; p++) {
            const float x0 = (&t[0].x)[p];
            const float x1 = (&t[1].x)[p];
            const float x2 = (&t[2].x)[p];
            const float x3 = (&t[3].x)[p];
            r[0] = fmaf(x0, x0, r[0]);
            r[1] = fmaf(x0, x1, r[1]);
            r[2] = fmaf(x0, x2, r[2]);
            r[3] = fmaf(x0, x3, r[3]);
            r[4] = fmaf(x1, x1, r[4]);
            r[5] = fmaf(x1, x2, r[5]);
            r[6] = fmaf(x1, x3, r[6]);
            r[7] = fmaf(x2, x2, r[7]);
            r[8] = fmaf(x2, x3, r[8]);
            r[9] = fmaf(x3, x3, r[9]);
            r[10] += x0; r[11] += x1; r[12] += x2; r[13] += x3;
        }

        #pragma unroll
        for (int c = 0; c < 4; c++)
            *reinterpret_cast<float4*>(&xt[row][c][w0]) = t[c];
    }

    // ---- Interleaved butterfly: 16 values over 32 lanes in 16 SHFL
    #pragma unroll
    for (int i = 0; i < 8; i++) {
        const float a = r[i], bb = r[i + 8];
        const float send = (lane & 16) ? a : bb;
        const float recv = __shfl_xor_sync(0xFFFFFFFFu, send, 16);
        r[i] = ((lane & 16) ? bb : a) + recv;
    }
    #pragma unroll
    for (int i = 0; i < 4; i++) {
        const float a = r[i], bb = r[i + 4];
        const float send = (lane & 8) ? a : bb;
        const float recv = __shfl_xor_sync(0xFFFFFFFFu, send, 8);
        r[i] = ((lane & 8) ? bb : a) + recv;
    }
    #pragma unroll
    for (int i = 0; i < 2; i++) {
        const float a = r[i], bb = r[i + 2];
        const float send = (lane & 4) ? a : bb;
        const float recv = __shfl_xor_sync(0xFFFFFFFFu, send, 4);
        r[i] = ((lane & 4) ? bb : a) + recv;
    }
    {
        const float a = r[0], bb = r[1];
        const float send = (lane & 2) ? a : bb;
        const float recv = __shfl_xor_sync(0xFFFFFFFFu, send, 2);
        r[0] = ((lane & 2) ? bb : a) + recv;
    }
    r[0] += __shfl_xor_sync(0xFFFFFFFFu, r[0], 1);
    if (!(lane & 1)) s_red[row][wrow][(lane >> 1) & 15] = r[0];
    __syncthreads();

    // ---- Epilogue: warp 0 handles row 0, warp 8 handles row 1 (concurrent)
    if (wrow == 0) {
        const int er = warp >> 3;          // row this warp finalizes
        if (lane < 16) {
            float s = 0.f;
            #pragma unroll
            for (int wdx = 0; wdx < 8; wdx++) s += s_red[er][wdx][lane];
            s_gm[er][lane] = s;
        }
        __syncwarp();

        if (lane < 16) {
            const int c = lane >> 2, d = lane & 3;
            const float m0 = s_gm[er][10], m1 = s_gm[er][11];
            const float m2 = s_gm[er][12], m3 = s_gm[er][13];
            float wqc[4], wkd[4];
            #pragma unroll
            for (int i = 0; i < 4; i++) {
                wqc[i] = __ldg(wq + c * 4 + i);
                wkd[i] = __ldg(wk + d * 4 + i);
            }
            const float bqc = __ldg(bq + c), bkd = __ldg(bk + d);

            float s = 0.f;
            #pragma unroll
            for (int i = 0; i < 4; i++) {
                float acc = 0.f;
                #pragma unroll
                for (int j = 0; j < 4; j++) {
                    const int lo = i < j ? i : j, hi = i < j ? j : i;
                    const int gi = lo * 4 - (lo * (lo - 1)) / 2 + (hi - lo);
                    acc = fmaf(s_gm[er][gi], wkd[j], acc);
                }
                s = fmaf(wqc[i], acc, s);
            }
            const float tq = wqc[0]*m0 + wqc[1]*m1 + wqc[2]*m2 + wqc[3]*m3;
            const float tk = wkd[0]*m0 + wkd[1]*m1 + wkd[2]*m2 + wkd[3]*m3;
            s += bqc * tk + bkd * tq + (float)W_DIM * bqc * bkd;
            s_sc[er][lane] = s * 0.03125f;   // 1/sqrt(1024)
        }
        __syncwarp();

        if (lane < 4) {
            const int c = lane;
            float m = s_sc[er][c * 4];
            #pragma unroll
            for (int d = 1; d < 4; d++) m = fmaxf(m, s_sc[er][c * 4 + d]);
            float e[4], sum = 0.f;
            #pragma unroll
            for (int d = 0; d < 4; d++) {
                e[d] = __expf(s_sc[er][c * 4 + d] - m);
                sum += e[d];
            }
            const float inv = __fdividef(1.0f, sum);
            #pragma unroll
            for (int d = 0; d < 4; d++) s_attn[er][c * 4 + d] = e[d] * inv;
        }
        __syncwarp();

        if (lane < 16) {
            const int c = lane >> 2, i = lane & 3;
            float s = 0.f;
            #pragma unroll
            for (int d = 0; d < 4; d++)
                s = fmaf(s_attn[er][c * 4 + d], __ldg(wv + d * 4 + i), s);
            s_fin[er][lane] = s;
        }
        if (lane < 4) {
            float s = 0.f;
            #pragma unroll
            for (int d = 0; d < 4; d++)
                s = fmaf(s_attn[er][lane * 4 + d], __ldg(bv + d), s);
            s_fin[er][16 + lane] = s;
        }
    }
    __syncthreads();

    // ---- Phase 2: re-read x from smem, out[c][w] = A_eff[c]·x[:,w] + b_eff[c]
    float ae[4][4], be[4];
    #pragma unroll
    for (int c = 0; c < 4; c++) {
        be[c] = s_fin[row][16 + c];
        #pragma unroll
        for (int i = 0; i < 4; i++) ae[c][i] = s_fin[row][c * 4 + i];
    }

    float4 xc[4];
    #pragma unroll
    for (int c = 0; c < 4; c++)
        xc[c] = *reinterpret_cast<const float4*>(&xt[row][c][w0]);

    const int bh = (b << 10) | h;
    const int obase = (bh << 12) + w0;
    #pragma unroll
    for (int c = 0; c < 4; c++) {
        float4 rr;
        float* rp = &rr.x;
        #pragma unroll
        for (int j = 0; j < 4; j++) {
            float s = be[c];
            #pragma unroll
            for (int i = 0; i < 4; i++)
                s = fmaf(ae[c][i], (&xc[i].x)[j], s);
            rp[j] = s;
        }
        __stcs(reinterpret_cast<float4*>(out + obase + (c << 10)), rr);
    }
}

extern "C" void kernel_launch(void* const* d_in, const int* in_sizes, int n_in,
                              void* d_out, int out_size)
{
    const float* x  = (const float*)d_in[0];
    const float* wq = (const float*)d_in[1];
    const float* bq = (const float*)d_in[2];
    const float* wk = (const float*)d_in[3];
    const float* bk = (const float*)d_in[4];
    const float* wv = (const float*)d_in[5];
    const float* bv = (const float*)d_in[6];
    float* out = (float*)d_out;

    dim3 grid(16 * (H_DIM / 2));   // 8192 CTAs, one per (b, h-pair)
    dim3 block(THREADS);
    fused_attn_kernel<<<grid, block>>>(x, wq, bq, wk, bk, wv, bv, out);
}